// round 13
// baseline (speedup 1.0000x reference)
#include <cuda_runtime.h>

// Canonical problem constants (safety never relies on them)
#define NLAT_   256
#define LMAXV   256
#define MMAXV   256
#define BCV     512          // BATCH*CH
#define NPOINTS 70144

#define X_ELEMS   35913728u  // 512 * 70144 floats
#define W_ELEMS   16777216u  // 256^3 floats
#define OUT_N     33554432u  // output: 512*256*256 float32 (REAL part only)

__host__ __device__ __forceinline__ unsigned cmin(unsigned a, unsigned b) {
    return a < b ? a : b;
}

// ---------------------------------------------------------------------------
// Stage 1: per-ring truncated real-DFT, COS (real) part only.
// Block = (ring k, bc-tile of 16). 256 threads; thread t owns m = t and
// accumulates 16 bc rows. Re X written into d_out at [bc*65536 + k*256 + m]
// (k parked in the l-slot). Every slot written (zeros for m >= mf).
// ---------------------------------------------------------------------------
__global__ void __launch_bounds__(256) dft_kernel(const float* __restrict__ x,
                                                  unsigned xcap,
                                                  float* outf,
                                                  unsigned ocap)
{
    const int k   = blockIdx.x;
    const int bc0 = blockIdx.y * 16;
    const int tid = threadIdx.x;

    int N, slon;
    if (k < 128) {
        N    = 4 * (k + 1) + 16;
        slon = 2 * k * k + 18 * k;
    } else {
        int q = 256 - k;
        N    = 4 * q + 16;
        slon = NPOINTS - (2 * q * q + 18 * q);
    }
    const int mf = (N / 2 + 1 < 256) ? (N / 2 + 1) : 256;

    __shared__ float sx[16 * 528];   // 33792 B
    __shared__ float twc[528];       //  2112 B

    for (int b = 0; b < 16; ++b) {
        unsigned base = (unsigned)(bc0 + b) * NPOINTS + (unsigned)slon;
        for (int n = tid; n < N; n += 256)
            sx[b * 528 + n] = x[cmin(base + (unsigned)n, xcap - 1u)];
    }
    const float ang = -6.28318530717958647692f / (float)N;
    for (int j = tid; j < N; j += 256) {
        int jj = (2 * j <= N) ? j : (j - N);   // angle in [-pi, pi]
        twc[j] = __cosf(ang * (float)jj);      // cos is even: sign irrelevant
    }
    __syncthreads();

    const int m = tid;
    float acc[16];
    #pragma unroll
    for (int b = 0; b < 16; ++b) acc[b] = 0.f;

    if (m < mf) {
        int j = 0;
        for (int n = 0; n < N; ++n) {
            float tc = twc[j];
            #pragma unroll
            for (int b = 0; b < 16; ++b)
                acc[b] = fmaf(sx[b * 528 + n], tc, acc[b]);
            j += m;                    // m <= N/2 < N: one subtract suffices
            if (j >= N) j -= N;
        }
        const float sc = 6.28318530717958647692f / (float)N;
        #pragma unroll
        for (int b = 0; b < 16; ++b) acc[b] *= sc;
    }

    // Writes: lane m contiguous -> fully coalesced 128B rows.
    #pragma unroll
    for (int b = 0; b < 16; ++b) {
        unsigned f = (unsigned)(bc0 + b) * 65536u + (unsigned)k * 256u
                     + (unsigned)m;
        outf[cmin(f, ocap - 1u)] = acc[b];
    }
}

// ---------------------------------------------------------------------------
// Stage 2: in-place per-(m, bc-tile-32) Legendre transform along k -> l.
//   out[bc, l, m] = sum_k w[m,l,k] * ReX[bc, k, m]
// Block caches its FULL read-set (32 bc x 256 k, 32 KB) in smem BEFORE
// writing l-results back to the same slots -> race-free in-place.
// Static smem (40.3 KB); all global indices clamped.
// ---------------------------------------------------------------------------
__global__ void __launch_bounds__(256) leg_kernel(const float* __restrict__ w,
                                                  unsigned wcap,
                                                  float* outf,
                                                  unsigned ocap)
{
    const int m   = blockIdx.x;
    const int bc0 = blockIdx.y * 32;
    const int tid = threadIdx.x;

    __shared__ float Xr[256 * 32];   // [k][bc] 32 KB
    __shared__ float Ws[32 * 65];    // [kk][l-tile 64], padded (8320 B)

    // Phase A: cache full read-set from d_out.
    for (int idx = tid; idx < 8192; idx += 256) {
        int kk = idx >> 5;
        int bc = bc0 + (idx & 31);
        unsigned fi = (unsigned)bc * 65536u + (unsigned)kk * 256u + (unsigned)m;
        Xr[idx] = outf[cmin(fi, ocap - 1u)];
    }

    const int bcl  = tid & 31;       // 0..31 == lane id -> conflict-free LDS
    const int lsub = tid >> 5;       // 0..7, 8 l-values each in a 64-tile
    const unsigned wmbase = (unsigned)m * 65536u;

    for (int l0 = 0; l0 < LMAXV; l0 += 64) {
        float c0 = 0.f, c1 = 0.f, c2 = 0.f, c3 = 0.f;
        float c4 = 0.f, c5 = 0.f, c6 = 0.f, c7 = 0.f;

        for (int k0 = 0; k0 < NLAT_; k0 += 32) {
            __syncthreads();         // phase A done / previous Ws readers done
            for (int idx = tid; idx < 2048; idx += 256) {
                int ll = idx >> 5;
                int kk = idx & 31;
                unsigned gw = wmbase + (unsigned)(l0 + ll) * 256u
                                     + (unsigned)(k0 + kk);
                Ws[kk * 65 + ll] = w[cmin(gw, wcap - 1u)];
            }
            __syncthreads();

            for (int kk = 0; kk < 32; ++kk) {
                float ar = Xr[(k0 + kk) * 32 + bcl];
                const float* wr = &Ws[kk * 65 + lsub * 8];
                c0 = fmaf(ar, wr[0], c0);
                c1 = fmaf(ar, wr[1], c1);
                c2 = fmaf(ar, wr[2], c2);
                c3 = fmaf(ar, wr[3], c3);
                c4 = fmaf(ar, wr[4], c4);
                c5 = fmaf(ar, wr[5], c5);
                c6 = fmaf(ar, wr[6], c6);
                c7 = fmaf(ar, wr[7], c7);
            }
        }

        // Write back in place: out[bc0+bcl, l, m]
        unsigned base = (unsigned)(bc0 + bcl) * 65536u + (unsigned)m
                        + (unsigned)(l0 + lsub * 8) * 256u;
        outf[cmin(base + 0u * 256u, ocap - 1u)] = c0;
        outf[cmin(base + 1u * 256u, ocap - 1u)] = c1;
        outf[cmin(base + 2u * 256u, ocap - 1u)] = c2;
        outf[cmin(base + 3u * 256u, ocap - 1u)] = c3;
        outf[cmin(base + 4u * 256u, ocap - 1u)] = c4;
        outf[cmin(base + 5u * 256u, ocap - 1u)] = c5;
        outf[cmin(base + 6u * 256u, ocap - 1u)] = c6;
        outf[cmin(base + 7u * 256u, ocap - 1u)] = c7;
    }
}

// ---------------------------------------------------------------------------
extern "C" void kernel_launch(void* const* d_in, const int* in_sizes, int n_in,
                              void* d_out, int out_size)
{
    if (n_in < 2 || !d_out) return;

    // x = largest input, w = second largest.
    int xi = 0, wi = -1;
    for (int i = 1; i < n_in; ++i)
        if (in_sizes[i] > in_sizes[xi]) xi = i;
    for (int i = 0; i < n_in; ++i)
        if (i != xi && (wi < 0 || in_sizes[i] > in_sizes[wi])) wi = i;

    const float* x = (const float*)d_in[xi];
    const float* w = (const float*)d_in[wi];
    float* outf = (float*)d_out;

    unsigned xcap = (in_sizes[xi] > 0) ? (unsigned)in_sizes[xi] : 1u;
    if (xcap > X_ELEMS) xcap = X_ELEMS;
    unsigned wcap = (in_sizes[wi] > 0) ? (unsigned)in_sizes[wi] : 1u;
    if (wcap > W_ELEMS) wcap = W_ELEMS;

    // PROVEN by R12: allocation = out_size elements (>=4B each); writing
    // <= out_size floats is safe. Logical output = 33.5M float32 (real part).
    unsigned ocap = (out_size > 0) ? (unsigned)out_size : 1u;
    if (ocap > OUT_N) ocap = OUT_N;

    dft_kernel<<<dim3(NLAT_, BCV / 16), 256>>>(x, xcap, outf, ocap);
    leg_kernel<<<dim3(MMAXV, BCV / 32), 256>>>(w, wcap, outf, ocap);
}